// round 1
// baseline (speedup 1.0000x reference)
#include <cuda_runtime.h>
#include <math.h>

#define B    8
#define QLEN 2048
#define D    1024
#define H    16
#define KV   256
#define HD   64
#define CDIM 1024

// Scratch (allocation-free rule: __device__ globals)
__device__ float g_Kvec[B * D];
__device__ float g_Vvec[B * D];
__device__ float g_cb[B];     // clip[b] . w2 + scale_b
__device__ float g_sumw1;     // sum(scale_w[:KV])

// ---------------------------------------------------------------------------
// Kernel 0: per-batch scalars. 1 block, 9 warps.
//   warps 0..7: cb[b] = sum_k clip[b,k]*scale_w[KV+k] + scale_b
//   warp 8:     sumw1 = sum_k scale_w[k]
// ---------------------------------------------------------------------------
__global__ void scalars_kernel(const float* __restrict__ clip,
                               const float* __restrict__ sw,
                               const float* __restrict__ sb) {
    int warp = threadIdx.x >> 5;
    int lane = threadIdx.x & 31;
    if (warp < B) {
        const int b = warp;
        float acc = 0.f;
        #pragma unroll
        for (int j = 0; j < KV / 32; j++) {
            int k = j * 32 + lane;
            acc += clip[b * KV + k] * sw[KV + k];
        }
        #pragma unroll
        for (int off = 16; off > 0; off >>= 1)
            acc += __shfl_xor_sync(0xffffffffu, acc, off);
        if (lane == 0) g_cb[b] = acc + sb[0];
    } else if (warp == 8) {
        float acc = 0.f;
        #pragma unroll
        for (int j = 0; j < KV / 32; j++)
            acc += sw[j * 32 + lane];
        #pragma unroll
        for (int off = 16; off > 0; off >>= 1)
            acc += __shfl_xor_sync(0xffffffffu, acc, off);
        if (lane == 0) g_sumw1 = acc;
    }
}

// ---------------------------------------------------------------------------
// Kernel 1: projections. Kvec[b,d] = key[b,:] . k_weight[d,:]  (and Vvec).
// grid = (D/8, 2): y=0 -> K, y=1 -> V. Block = 256 (8 warps), warp per d,
// all 8 batches per warp (weights read once, coalesced along c).
// ---------------------------------------------------------------------------
__global__ void proj_kernel(const float* __restrict__ key,
                            const float* __restrict__ value,
                            const float* __restrict__ kw,
                            const float* __restrict__ vw) {
    __shared__ float act[B * CDIM];  // 32 KB
    const float* src = (blockIdx.y == 0) ? key : value;
    const float* w   = (blockIdx.y == 0) ? kw  : vw;
    float*       dst = (blockIdx.y == 0) ? g_Kvec : g_Vvec;

    for (int i = threadIdx.x; i < B * CDIM; i += blockDim.x)
        act[i] = src[i];
    __syncthreads();

    int warp = threadIdx.x >> 5;
    int lane = threadIdx.x & 31;
    int d = blockIdx.x * 8 + warp;

    float acc[B];
    #pragma unroll
    for (int b = 0; b < B; b++) acc[b] = 0.f;

    const float* wrow = w + (size_t)d * CDIM;
    for (int c = lane; c < CDIM; c += 32) {
        float wv = wrow[c];
        #pragma unroll
        for (int b = 0; b < B; b++)
            acc[b] = fmaf(wv, act[b * CDIM + c], acc[b]);
    }
    #pragma unroll
    for (int b = 0; b < B; b++) {
        #pragma unroll
        for (int off = 16; off > 0; off >>= 1)
            acc[b] += __shfl_xor_sync(0xffffffffu, acc[b], off);
    }
    if (lane == 0) {
        #pragma unroll
        for (int b = 0; b < B; b++)
            dst[b * D + d] = acc[b];
    }
}

// ---------------------------------------------------------------------------
// Kernel 2: out[b,q,:] = Vvec[b,:]  (pure broadcast, 64 MB write)
// grid = (QLEN, B), 256 threads, float4 per thread.
// ---------------------------------------------------------------------------
__global__ void outb_kernel(float* __restrict__ out) {
    int q = blockIdx.x, b = blockIdx.y;
    const float4* v = reinterpret_cast<const float4*>(g_Vvec + b * D);
    float4* o = reinterpret_cast<float4*>(out) + ((size_t)b * QLEN + q) * (D / 4);
    o[threadIdx.x] = v[threadIdx.x];
}

// ---------------------------------------------------------------------------
// Kernel 3: attention weights.
//   s0   = Q[b,q,h*64:] . Kvec[b,h*64:] / 8
//   lin  = s0 * sumw1 + cb[b]
//   attn = softmax_k( lin * clip[b,k] )     (s0 shift cancels in softmax)
// grid = (QLEN/8, H, B), block = 256 (warp per q).
// ---------------------------------------------------------------------------
__global__ void attn_kernel(const float* __restrict__ q,
                            const float* __restrict__ clip,
                            float* __restrict__ attn) {
    const int b = blockIdx.z, h = blockIdx.y;
    __shared__ float s_clip[KV];
    __shared__ float s_kv[HD];
    __shared__ float s_cb, s_sw;

    if (threadIdx.x < KV) s_clip[threadIdx.x] = clip[b * KV + threadIdx.x];
    if (threadIdx.x < HD) s_kv[threadIdx.x] = g_Kvec[b * D + h * HD + threadIdx.x];
    if (threadIdx.x == 0) { s_cb = g_cb[b]; s_sw = g_sumw1; }
    __syncthreads();

    int warp = threadIdx.x >> 5;
    int lane = threadIdx.x & 31;
    int qi = blockIdx.x * 8 + warp;

    // 64-float contiguous Q slice per warp: float2 per lane (256B coalesced)
    const float* qr = q + ((size_t)b * QLEN + qi) * D + h * HD;
    float2 qv = reinterpret_cast<const float2*>(qr)[lane];
    float dot = qv.x * s_kv[2 * lane] + qv.y * s_kv[2 * lane + 1];
    #pragma unroll
    for (int off = 16; off > 0; off >>= 1)
        dot += __shfl_xor_sync(0xffffffffu, dot, off);

    float s0  = dot * 0.125f;            // 1/sqrt(64)
    float lin = fmaf(s0, s_sw, s_cb);

    float pv[KV / 32];
    float m = -INFINITY;
    #pragma unroll
    for (int j = 0; j < KV / 32; j++) {
        pv[j] = lin * s_clip[j * 32 + lane];
        m = fmaxf(m, pv[j]);
    }
    #pragma unroll
    for (int off = 16; off > 0; off >>= 1)
        m = fmaxf(m, __shfl_xor_sync(0xffffffffu, m, off));

    float sum = 0.f;
    #pragma unroll
    for (int j = 0; j < KV / 32; j++) {
        pv[j] = __expf(pv[j] - m);
        sum += pv[j];
    }
    #pragma unroll
    for (int off = 16; off > 0; off >>= 1)
        sum += __shfl_xor_sync(0xffffffffu, sum, off);
    float inv = __frcp_rn(sum);

    float* orow = attn + (((size_t)(b * H + h) * QLEN + qi) * KV);
    #pragma unroll
    for (int j = 0; j < KV / 32; j++)
        orow[j * 32 + lane] = pv[j] * inv;   // 1KB coalesced per warp
}

// ---------------------------------------------------------------------------
extern "C" void kernel_launch(void* const* d_in, const int* in_sizes, int n_in,
                              void* d_out, int out_size) {
    const float* query = (const float*)d_in[0];
    const float* key   = (const float*)d_in[1];
    const float* value = (const float*)d_in[2];
    const float* clip  = (const float*)d_in[3];
    const float* kw    = (const float*)d_in[4];
    const float* vw    = (const float*)d_in[5];
    const float* sw    = (const float*)d_in[6];
    const float* sb    = (const float*)d_in[7];
    float* out = (float*)d_out;

    scalars_kernel<<<1, 288>>>(clip, sw, sb);
    proj_kernel<<<dim3(D / 8, 2), 256>>>(key, value, kw, vw);
    outb_kernel<<<dim3(QLEN, B), 256>>>(out);

    const long long out_elems  = (long long)B * QLEN * D;        // 16777216
    const long long attn_elems = (long long)B * H * QLEN * KV;   // 16777216
    if ((long long)out_size >= out_elems + attn_elems) {
        float* attn = out + out_elems;
        attn_kernel<<<dim3(QLEN / 8, H, B), 256>>>(query, clip, attn);
    }
}

// round 3
// speedup vs baseline: 1.0491x; 1.0491x over previous
#include <cuda_runtime.h>
#include <math.h>

#define B    8
#define QLEN 2048
#define D    1024
#define H    16
#define KV   256
#define HD   64
#define CDIM 1024
#define L2E  1.4426950408889634f

// Scratch (allocation-free rule: __device__ globals)
__device__ float g_Kvec[B * D];
__device__ float g_Vvec[B * D];
__device__ float g_cb[B];       // clip[b] . w2 + scale_b
__device__ float g_cmax[B];     // max_k clip[b,k]
__device__ float g_cmin[B];     // min_k clip[b,k]
__device__ float g_sumw1;       // sum(scale_w[:KV])

// ---------------------------------------------------------------------------
// Kernel 0: per-batch scalars. 1 block, 9 warps.
//   warps 0..7: cb[b], cmax[b], cmin[b]
//   warp 8:     sumw1
// ---------------------------------------------------------------------------
__global__ void scalars_kernel(const float* __restrict__ clip,
                               const float* __restrict__ sw,
                               const float* __restrict__ sb) {
    int warp = threadIdx.x >> 5;
    int lane = threadIdx.x & 31;
    if (warp < B) {
        const int b = warp;
        float acc = 0.f, mx = -INFINITY, mn = INFINITY;
        #pragma unroll
        for (int j = 0; j < KV / 32; j++) {
            int k = j * 32 + lane;
            float c = clip[b * KV + k];
            acc += c * sw[KV + k];
            mx = fmaxf(mx, c);
            mn = fminf(mn, c);
        }
        #pragma unroll
        for (int off = 16; off > 0; off >>= 1) {
            acc += __shfl_xor_sync(0xffffffffu, acc, off);
            mx = fmaxf(mx, __shfl_xor_sync(0xffffffffu, mx, off));
            mn = fminf(mn, __shfl_xor_sync(0xffffffffu, mn, off));
        }
        if (lane == 0) {
            g_cb[b]   = acc + sb[0];
            g_cmax[b] = mx;
            g_cmin[b] = mn;
        }
    } else if (warp == 8) {
        float acc = 0.f;
        #pragma unroll
        for (int j = 0; j < KV / 32; j++)
            acc += sw[j * 32 + lane];
        #pragma unroll
        for (int off = 16; off > 0; off >>= 1)
            acc += __shfl_xor_sync(0xffffffffu, acc, off);
        if (lane == 0) g_sumw1 = acc;
    }
}

// ---------------------------------------------------------------------------
// Kernel 1: projections. Kvec[b,d] = key[b,:] . k_weight[d,:]  (and Vvec).
// grid = (D/8, 2): y=0 -> K, y=1 -> V. Block = 256 (8 warps), warp per d.
// ---------------------------------------------------------------------------
__global__ void proj_kernel(const float* __restrict__ key,
                            const float* __restrict__ value,
                            const float* __restrict__ kw,
                            const float* __restrict__ vw) {
    __shared__ float act[B * CDIM];  // 32 KB
    const float* src = (blockIdx.y == 0) ? key : value;
    const float* w   = (blockIdx.y == 0) ? kw  : vw;
    float*       dst = (blockIdx.y == 0) ? g_Kvec : g_Vvec;

    for (int i = threadIdx.x; i < B * CDIM; i += blockDim.x)
        act[i] = src[i];
    __syncthreads();

    int warp = threadIdx.x >> 5;
    int lane = threadIdx.x & 31;
    int d = blockIdx.x * 8 + warp;

    float acc[B];
    #pragma unroll
    for (int b = 0; b < B; b++) acc[b] = 0.f;

    const float* wrow = w + (size_t)d * CDIM;
    for (int c = lane; c < CDIM; c += 32) {
        float wv = wrow[c];
        #pragma unroll
        for (int b = 0; b < B; b++)
            acc[b] = fmaf(wv, act[b * CDIM + c], acc[b]);
    }
    #pragma unroll
    for (int b = 0; b < B; b++) {
        #pragma unroll
        for (int off = 16; off > 0; off >>= 1)
            acc[b] += __shfl_xor_sync(0xffffffffu, acc[b], off);
    }
    if (lane == 0) {
        #pragma unroll
        for (int b = 0; b < B; b++)
            dst[b * D + d] = acc[b];
    }
}

// ---------------------------------------------------------------------------
// Kernel 2: fused attn + out-broadcast.
//   lin   = (Q[b,q,h*64:] . Kvec[b,h*64:] / 8) * sumw1 + cb[b]
//   m     = lin * (lin>0 ? cmax : cmin)                  (clip > 0)
//   attn  = exp2(lin*clip_k*L2E - m*L2E) / sum
//   out[b,q, h*64 : h*64+64] = Vvec[b, h*64 : ...]       (block's slice)
// grid = (QLEN/8, H, B), block = 256 (warp per q).
// Each lane owns the contiguous k-slice [lane*8, lane*8+8) -> 2x STG.128.
// ---------------------------------------------------------------------------
__global__ void __launch_bounds__(256)
attn_kernel(const float* __restrict__ q,
            const float* __restrict__ clip,
            float* __restrict__ out,
            float* __restrict__ attn) {
    const int b = blockIdx.z, h = blockIdx.y;
    __shared__ float s_sc[KV];   // clip * log2(e)
    __shared__ float s_kv[HD];
    __shared__ float s_vv[HD];
    __shared__ float s_cb, s_sw, s_cmx, s_cmn;

    const int warp = threadIdx.x >> 5;
    const int lane = threadIdx.x & 31;
    const int qi = blockIdx.x * 8 + warp;

    // Issue the global Q load first (independent of smem fill).
    const float* qr = q + ((size_t)b * QLEN + qi) * D + h * HD;
    float2 qv = __ldg(reinterpret_cast<const float2*>(qr) + lane);

    if (threadIdx.x < KV) s_sc[threadIdx.x] = clip[b * KV + threadIdx.x] * L2E;
    if (threadIdx.x < HD) {
        s_kv[threadIdx.x] = g_Kvec[b * D + h * HD + threadIdx.x];
        s_vv[threadIdx.x] = g_Vvec[b * D + h * HD + threadIdx.x];
    }
    if (threadIdx.x == 0) {
        s_cb = g_cb[b]; s_sw = g_sumw1;
        s_cmx = g_cmax[b]; s_cmn = g_cmin[b];
    }
    __syncthreads();

    // out broadcast: this block's 256B slice of each of its 8 out rows
    {
        float2 vv = make_float2(s_vv[2 * lane], s_vv[2 * lane + 1]);
        float2* orow = reinterpret_cast<float2*>(
            out + ((size_t)b * QLEN + qi) * D + h * HD);
        orow[lane] = vv;
    }

    float dot = qv.x * s_kv[2 * lane] + qv.y * s_kv[2 * lane + 1];
    #pragma unroll
    for (int off = 16; off > 0; off >>= 1)
        dot += __shfl_xor_sync(0xffffffffu, dot, off);

    float s0  = dot * 0.125f;                 // 1/sqrt(64)
    float lin = fmaf(s0, s_sw, s_cb);
    float m2  = lin * (lin > 0.f ? s_cmx : s_cmn) * L2E;   // max in log2 units

    // Lane-contiguous k-slice: k = lane*8 + j
    const float4* sc4 = reinterpret_cast<const float4*>(s_sc) + lane * 2;
    float4 c0 = sc4[0], c1 = sc4[1];

    float pv[8];
    pv[0] = exp2f(fmaf(lin, c0.x, -m2));
    pv[1] = exp2f(fmaf(lin, c0.y, -m2));
    pv[2] = exp2f(fmaf(lin, c0.z, -m2));
    pv[3] = exp2f(fmaf(lin, c0.w, -m2));
    pv[4] = exp2f(fmaf(lin, c1.x, -m2));
    pv[5] = exp2f(fmaf(lin, c1.y, -m2));
    pv[6] = exp2f(fmaf(lin, c1.z, -m2));
    pv[7] = exp2f(fmaf(lin, c1.w, -m2));

    float sum = ((pv[0] + pv[1]) + (pv[2] + pv[3]))
              + ((pv[4] + pv[5]) + (pv[6] + pv[7]));
    #pragma unroll
    for (int off = 16; off > 0; off >>= 1)
        sum += __shfl_xor_sync(0xffffffffu, sum, off);
    float inv = __frcp_rn(sum);

    float4* orow4 = reinterpret_cast<float4*>(
        attn + (((size_t)(b * H + h) * QLEN + qi) * KV)) + lane * 2;
    orow4[0] = make_float4(pv[0] * inv, pv[1] * inv, pv[2] * inv, pv[3] * inv);
    orow4[1] = make_float4(pv[4] * inv, pv[5] * inv, pv[6] * inv, pv[7] * inv);
}

// ---------------------------------------------------------------------------
extern "C" void kernel_launch(void* const* d_in, const int* in_sizes, int n_in,
                              void* d_out, int out_size) {
    const float* query = (const float*)d_in[0];
    const float* key   = (const float*)d_in[1];
    const float* value = (const float*)d_in[2];
    const float* clip  = (const float*)d_in[3];
    const float* kw    = (const float*)d_in[4];
    const float* vw    = (const float*)d_in[5];
    const float* sw    = (const float*)d_in[6];
    const float* sb    = (const float*)d_in[7];
    float* out = (float*)d_out;

    scalars_kernel<<<1, 288>>>(clip, sw, sb);
    proj_kernel<<<dim3(D / 8, 2), 256>>>(key, value, kw, vw);

    const long long out_elems  = (long long)B * QLEN * D;        // 16777216
    float* attn = out + out_elems;
    attn_kernel<<<dim3(QLEN / 8, H, B), 256>>>(query, clip, out, attn);
}